// round 1
// baseline (speedup 1.0000x reference)
#include <cuda_runtime.h>
#include <cuda_bf16.h>

// FWHT-4096 over fp32 rows. 256 threads/CTA, 16 elems/thread, radix-16 x 3 rounds.
// Smem padded addr = e + (e>>4) to kill bank conflicts on the transposed rounds.

#define FWHT_N       4096
#define FWHT_THREADS 256
#define SMEM_FLOATS  4352   // 4096 + 256 pad (max addr 4350)

__device__ __forceinline__ void butterfly16(float v[16]) {
    // 4 WHT stages over the 4 register-index bits (stage order is irrelevant:
    // H = H2^{ox12}, all bit-stages commute).
#pragma unroll
    for (int b = 1; b < 16; b <<= 1) {
#pragma unroll
        for (int k = 0; k < 16; k++) {
            if (!(k & b)) {
                float a = v[k];
                float c = v[k | b];
                v[k]     = a + c;
                v[k | b] = a - c;
            }
        }
    }
}

__global__ __launch_bounds__(FWHT_THREADS)
void QHadamard_40243843564239_kernel(const float* __restrict__ x,
                                     float* __restrict__ out) {
    __shared__ float s[SMEM_FLOATS];

    const int row = blockIdx.x;
    const float* __restrict__ xin  = x   + (size_t)row * FWHT_N;
    float* __restrict__       yout = out + (size_t)row * FWHT_N;

    const int t = threadIdx.x;
    float v[16];

    // ---- Round 1: element bits 0..3 in registers. e = 16*t + k ----
    // Coalesced: 4x LDG.128 per thread, warp covers 2048 contiguous bytes/ld.
    const float4* __restrict__ x4 = reinterpret_cast<const float4*>(xin + 16 * t);
#pragma unroll
    for (int q = 0; q < 4; q++) {
        float4 f = x4[q];
        v[4 * q + 0] = f.x;
        v[4 * q + 1] = f.y;
        v[4 * q + 2] = f.z;
        v[4 * q + 3] = f.w;
    }
    butterfly16(v);

    // smem addr for e = 16t+k:  e + (e>>4) = 17t + k   (conflict-free per warp)
    {
        const int base = 17 * t;
#pragma unroll
        for (int k = 0; k < 16; k++) s[base + k] = v[k];
    }
    __syncthreads();

    // ---- Round 2: element bits 4..7 in registers. ----
    // e = i | (k<<4) | (w<<8),  i = t[0:4), w = t[4:8)
    // addr = e + (e>>4) = i + 17k + 272w   (banks i and i+16 within a warp: CF)
    {
        const int i = t & 15;
        const int w = t >> 4;
        const int base = i + 272 * w;
#pragma unroll
        for (int k = 0; k < 16; k++) v[k] = s[base + 17 * k];
        butterfly16(v);
        // write back to the exact addresses this thread read: no sync needed
        // between the read and write of the same round.
#pragma unroll
        for (int k = 0; k < 16; k++) s[base + 17 * k] = v[k];
    }
    __syncthreads();

    // ---- Round 3: element bits 8..11 in registers. e = t + 256k ----
    // addr = t + (t>>4) + 272k   (single 2-way collision t=0/t=31: negligible)
    {
        const int base = t + (t >> 4);
#pragma unroll
        for (int k = 0; k < 16; k++) v[k] = s[base + 272 * k];
        butterfly16(v);

        const float scale = 0.015625f;  // 1/sqrt(4096)
        // Coalesced stores: for each k, warp writes 128 contiguous bytes.
#pragma unroll
        for (int k = 0; k < 16; k++) yout[t + 256 * k] = v[k] * scale;
    }
}

extern "C" void kernel_launch(void* const* d_in, const int* in_sizes, int n_in,
                              void* d_out, int out_size) {
    const float* x = (const float*)d_in[0];
    float* out = (float*)d_out;
    const int rows = in_sizes[0] / FWHT_N;   // 4*2048 = 8192
    QHadamard_40243843564239_kernel<<<rows, FWHT_THREADS>>>(x, out);
}

// round 2
// speedup vs baseline: 1.0423x; 1.0423x over previous
#include <cuda_runtime.h>
#include <cuda_bf16.h>

// FWHT-4096 fp32. 256 threads/CTA, 16 elems/thread, radix-16 x 3 rounds.
// XOR-swizzled smem layout: loc(e) = e ^ (((e>>5)&3)<<2) ^ (((e>>8)&1)<<4)
// -> conflict-free on ALL rounds AND 16B-aligned for STS.128 in round 1.

#define FWHT_N       4096
#define FWHT_THREADS 256

__device__ __forceinline__ void butterfly16(float v[16]) {
#pragma unroll
    for (int b = 1; b < 16; b <<= 1) {
#pragma unroll
        for (int k = 0; k < 16; k++) {
            if (!(k & b)) {
                float a = v[k];
                float c = v[k | b];
                v[k]     = a + c;
                v[k | b] = a - c;
            }
        }
    }
}

__global__ __launch_bounds__(FWHT_THREADS)
void QHadamard_40243843564239_kernel(const float* __restrict__ x,
                                     float* __restrict__ out) {
    __shared__ float s[FWHT_N];

    const int row = blockIdx.x;
    const float* __restrict__ xin  = x   + (size_t)row * FWHT_N;
    float* __restrict__       yout = out + (size_t)row * FWHT_N;

    const int t = threadIdx.x;
    const int i = t & 15;          // element bits 0-3 (rounds 2,3)
    const int w = t >> 4;          // element bits 8-11 (round 2) / 4-7 (round 3)
    float v[16];

    // ---- Round 1: bits 0..3 in regs. e = 16t + k. Streaming LDG.128. ----
    const float4* __restrict__ x4 = reinterpret_cast<const float4*>(xin + 16 * t);
#pragma unroll
    for (int q = 0; q < 4; q++) {
        float4 f = __ldcs(x4 + q);
        v[4 * q + 0] = f.x;
        v[4 * q + 1] = f.y;
        v[4 * q + 2] = f.z;
        v[4 * q + 3] = f.w;
    }
    butterfly16(v);

    // Swizzled write: loc = 16*(t ^ ((t>>4)&1)) + 4*(q ^ ((t>>1)&3)) + r
    // 4x STS.128, conflict-free (each octet of lanes covers 8 distinct bank-quads).
    {
        float4* sb = reinterpret_cast<float4*>(&s[16 * (t ^ ((t >> 4) & 1))]);
        const int tq = (t >> 1) & 3;
#pragma unroll
        for (int q = 0; q < 4; q++) {
            sb[q ^ tq] = make_float4(v[4 * q], v[4 * q + 1], v[4 * q + 2], v[4 * q + 3]);
        }
    }
    __syncthreads();

    // ---- Round 2: bits 4..7 in regs. e = i + 16k + 256w. ----
    // loc = (i ^ (4*((k>>1)&3))) + 16*(k ^ (w&1)) + 256w  -> CF scalar LDS/STS.
    {
        const int wbit = w & 1;
        const int base = 256 * w;
#pragma unroll
        for (int k = 0; k < 16; k++) {
            const int loc = (i ^ (((k >> 1) & 3) << 2)) + ((k ^ wbit) << 4) + base;
            v[k] = s[loc];
        }
        butterfly16(v);
#pragma unroll
        for (int k = 0; k < 16; k++) {
            const int loc = (i ^ (((k >> 1) & 3) << 2)) + ((k ^ wbit) << 4) + base;
            s[loc] = v[k];
        }
    }
    __syncthreads();

    // ---- Round 3: bits 8..11 in regs. e = t + 256k = i + 16j + 256k. ----
    // loc = (i ^ (4*((j>>1)&3))) + 16*(j ^ (k&1)) + 256k  -> CF scalar LDS.
    {
        const int j  = w;                       // t>>4
        const int ci = i ^ (((j >> 1) & 3) << 2);
#pragma unroll
        for (int k = 0; k < 16; k++) {
            const int loc = ci + ((j ^ (k & 1)) << 4) + (k << 8);
            v[k] = s[loc];
        }
        butterfly16(v);

        const float scale = 0.015625f;  // 1/sqrt(4096)
        // Coalesced streaming stores: per k, warp writes 128 contiguous bytes.
#pragma unroll
        for (int k = 0; k < 16; k++) {
            __stcs(&yout[t + 256 * k], v[k] * scale);
        }
    }
}

extern "C" void kernel_launch(void* const* d_in, const int* in_sizes, int n_in,
                              void* d_out, int out_size) {
    const float* x = (const float*)d_in[0];
    float* out = (float*)d_out;
    const int rows = in_sizes[0] / FWHT_N;   // 8192
    QHadamard_40243843564239_kernel<<<rows, FWHT_THREADS>>>(x, out);
}